// round 2
// baseline (speedup 1.0000x reference)
#include <cuda_runtime.h>
#include <cuda_bf16.h>
#include <math.h>

// Problem constants
#define BB 2
#define SS 2048
#define DD 2048
#define HH 16
#define NOPE 128
#define ROPE 64
#define VD 128
#define KV_RANK 512
#define Q_RANK 1536
#define RR (BB*SS)          // 4096 rows
#define QD (NOPE+ROPE)      // 192
#define HQ (HH*QD)          // 3072
#define KVD (NOPE+VD)       // 256
#define HKV (HH*KVD)        // 4096
#define CKVW (KV_RANK+ROPE) // 576
#define OW (HH*VD)          // 2048

// Scratch (device globals per allocation-guard rules)
__device__ float g_qa [(size_t)RR*Q_RANK];
__device__ float g_q  [(size_t)RR*HQ];
__device__ float g_ckv[(size_t)RR*CKVW];
__device__ float g_kv [(size_t)RR*HKV];
__device__ float g_o  [(size_t)RR*OW];

// ---------------------------------------------------------------------------
// SGEMM: C[M,N] = A[M,K] @ B[K,N], row-major, 128x128 tile, 8x8/thread
// ---------------------------------------------------------------------------
#define BM 128
#define BN 128
#define BK 16

__global__ __launch_bounds__(256) void sgemm_k(
    const float* __restrict__ A, const float* __restrict__ B, float* __restrict__ C,
    int M, int N, int K, int lda, int ldb, int ldc)
{
    __shared__ float As[BK][BM];
    __shared__ float Bs[BK][BN];
    const int tid = threadIdx.x;
    const int tx = tid & 15, ty = tid >> 4;
    const int m0 = blockIdx.y * BM, n0 = blockIdx.x * BN;

    float acc[8][8];
    #pragma unroll
    for (int i = 0; i < 8; i++)
        #pragma unroll
        for (int j = 0; j < 8; j++) acc[i][j] = 0.f;

    for (int kt = 0; kt < K; kt += BK) {
        // A tile: BM x BK, store transposed As[k][m]
        #pragma unroll
        for (int u = 0; u < 2; u++) {
            int idx = tid + u * 256;          // 0..511
            int row = idx >> 2;               // 0..127
            int c4  = (idx & 3) * 4;          // 0,4,8,12
            int ar = m0 + row;
            float4 v = make_float4(0.f,0.f,0.f,0.f);
            if (ar < M)
                v = *reinterpret_cast<const float4*>(A + (size_t)ar*lda + kt + c4);
            As[c4+0][row] = v.x; As[c4+1][row] = v.y;
            As[c4+2][row] = v.z; As[c4+3][row] = v.w;
        }
        // B tile: BK x BN
        #pragma unroll
        for (int u = 0; u < 2; u++) {
            int idx = tid + u * 256;
            int row = idx >> 5;               // 0..15
            int c4  = (idx & 31) * 4;         // 0..124
            int bc = n0 + c4;
            float4 v = make_float4(0.f,0.f,0.f,0.f);
            if (bc < N)
                v = *reinterpret_cast<const float4*>(B + (size_t)(kt+row)*ldb + bc);
            *reinterpret_cast<float4*>(&Bs[row][c4]) = v;
        }
        __syncthreads();
        #pragma unroll
        for (int k = 0; k < BK; k++) {
            float a[8], b[8];
            *(float4*)&a[0] = *(const float4*)&As[k][ty*8];
            *(float4*)&a[4] = *(const float4*)&As[k][ty*8+4];
            *(float4*)&b[0] = *(const float4*)&Bs[k][tx*8];
            *(float4*)&b[4] = *(const float4*)&Bs[k][tx*8+4];
            #pragma unroll
            for (int i = 0; i < 8; i++)
                #pragma unroll
                for (int j = 0; j < 8; j++)
                    acc[i][j] = fmaf(a[i], b[j], acc[i][j]);
        }
        __syncthreads();
    }
    #pragma unroll
    for (int i = 0; i < 8; i++) {
        int cr = m0 + ty*8 + i;
        if (cr >= M) continue;
        #pragma unroll
        for (int j = 0; j < 8; j++) {
            int cc = n0 + tx*8 + j;
            if (cc < N) C[(size_t)cr*ldc + cc] = acc[i][j];
        }
    }
}

// ---------------------------------------------------------------------------
// RMSNorm (in place): x[row, 0:n] *= rsqrt(mean(x^2)+eps) * w
// ---------------------------------------------------------------------------
__global__ __launch_bounds__(256) void rmsnorm_k(
    float* __restrict__ x, const float* __restrict__ w, int n, int stride)
{
    int row = blockIdx.x;
    float* p = x + (size_t)row * stride;
    float ss = 0.f;
    for (int i = threadIdx.x; i < n; i += 256) { float v = p[i]; ss += v*v; }
    __shared__ float red[256];
    red[threadIdx.x] = ss;
    __syncthreads();
    for (int s2 = 128; s2 > 0; s2 >>= 1) {
        if (threadIdx.x < s2) red[threadIdx.x] += red[threadIdx.x + s2];
        __syncthreads();
    }
    float r = rsqrtf(red[0] / (float)n + 1e-6f);
    for (int i = threadIdx.x; i < n; i += 256) p[i] = p[i] * r * w[i];
}

// ---------------------------------------------------------------------------
// RoPE
// ---------------------------------------------------------------------------
__global__ void rope_q_k()
{
    int t = blockIdx.x * blockDim.x + threadIdx.x;   // RR*HH*32
    int i = t & 31;
    int h = (t >> 5) & (HH-1);
    int r = t >> 9;
    int s = r & (SS-1);
    float inv = (float)pow(10000.0, -(double)(2*i) / 64.0);
    float ang = (float)s * inv;
    float sn, cs;
    sincosf(ang, &sn, &cs);
    float* p = &g_q[(size_t)r*HQ + h*QD + NOPE + i];
    float x1 = p[0], x2 = p[32];
    p[0]  = x1*cs - x2*sn;
    p[32] = x2*cs + x1*sn;
}

__global__ void rope_kpe_k()
{
    int t = blockIdx.x * blockDim.x + threadIdx.x;   // RR*32
    int i = t & 31;
    int r = t >> 5;
    int s = r & (SS-1);
    float inv = (float)pow(10000.0, -(double)(2*i) / 64.0);
    float ang = (float)s * inv;
    float sn, cs;
    sincosf(ang, &sn, &cs);
    float* p = &g_ckv[(size_t)r*CKVW + KV_RANK + i];
    float x1 = p[0], x2 = p[32];
    p[0]  = x1*cs - x2*sn;
    p[32] = x2*cs + x1*sn;
}

// ---------------------------------------------------------------------------
// Flash attention (causal). Block = 8 warps = 8 query rows of one (b,h).
// K-tile of 32 keys in SMEM, online softmax, o[128] split 4 floats/lane.
// ---------------------------------------------------------------------------
__global__ __launch_bounds__(256) void flash_k()
{
    __shared__ float Qs[8][196];
    __shared__ float Ks[32][196];
    __shared__ float Vs[32][128];

    const int b = blockIdx.z, h = blockIdx.y;
    const int q0 = blockIdx.x * 8;
    const int tid = threadIdx.x;
    const int w = tid >> 5, lane = tid & 31;

    // Load Q tile (rope already applied to g_q)
    for (int idx = tid; idx < 8*192; idx += 256) {
        int row = idx / 192, d = idx - row*192;
        Qs[row][d] = g_q[(size_t)(b*SS + q0 + row)*HQ + h*QD + d];
    }

    const int qi = q0 + w;
    float m = -1e30f, l = 0.f;
    float o0 = 0.f, o1 = 0.f, o2 = 0.f, o3 = 0.f;
    const float scale = rsqrtf((float)QD);
    const int ntiles = (q0 + 7) / 32 + 1;

    for (int kt = 0; kt < ntiles; kt++) {
        const int k0 = kt * 32;
        __syncthreads();
        // K tile: k_nope from g_kv, k_pe (roped, shared across heads) from g_ckv
        for (int idx = tid; idx < 32*192; idx += 256) {
            int j = idx / 192, d = idx - j*192;
            size_t rk = (size_t)(b*SS + k0 + j);
            Ks[j][d] = (d < NOPE) ? g_kv[rk*HKV + h*KVD + d]
                                  : g_ckv[rk*CKVW + KV_RANK + (d - NOPE)];
        }
        // V tile
        for (int idx = tid; idx < 32*128; idx += 256) {
            int j = idx >> 7, d = idx & 127;
            Vs[j][d] = g_kv[(size_t)(b*SS + k0 + j)*HKV + h*KVD + NOPE + d];
        }
        __syncthreads();

        // Score for key (k0+lane) vs query qi
        float s = 0.f;
        const float4* kp = (const float4*)&Ks[lane][0];
        const float4* qp = (const float4*)&Qs[w][0];
        #pragma unroll
        for (int d4 = 0; d4 < 48; d4++) {
            float4 kk = kp[d4], qq = qp[d4];
            s = fmaf(kk.x, qq.x, s);
            s = fmaf(kk.y, qq.y, s);
            s = fmaf(kk.z, qq.z, s);
            s = fmaf(kk.w, qq.w, s);
        }
        s *= scale;
        if (k0 + lane > qi) s = -1e30f;

        float smax = s;
        #pragma unroll
        for (int off = 16; off; off >>= 1)
            smax = fmaxf(smax, __shfl_xor_sync(0xffffffffu, smax, off));
        float mnew = fmaxf(m, smax);
        float alpha = __expf(m - mnew);
        float p = __expf(s - mnew);
        float ps = p;
        #pragma unroll
        for (int off = 16; off; off >>= 1)
            ps += __shfl_xor_sync(0xffffffffu, ps, off);
        l = l * alpha + ps;
        o0 *= alpha; o1 *= alpha; o2 *= alpha; o3 *= alpha;
        m = mnew;

        #pragma unroll
        for (int j = 0; j < 32; j++) {
            float wj = __shfl_sync(0xffffffffu, p, j);
            o0 = fmaf(wj, Vs[j][lane      ], o0);
            o1 = fmaf(wj, Vs[j][lane + 32 ], o1);
            o2 = fmaf(wj, Vs[j][lane + 64 ], o2);
            o3 = fmaf(wj, Vs[j][lane + 96 ], o3);
        }
    }

    float inv = 1.f / l;
    float* op = &g_o[(size_t)(b*SS + qi)*OW + h*VD];
    op[lane      ] = o0 * inv;
    op[lane + 32 ] = o1 * inv;
    op[lane + 64 ] = o2 * inv;
    op[lane + 96 ] = o3 * inv;
}

// ---------------------------------------------------------------------------
// Launch
// ---------------------------------------------------------------------------
extern "C" void kernel_launch(void* const* d_in, const int* in_sizes, int n_in,
                              void* d_out, int out_size)
{
    const float* x         = (const float*)d_in[0];
    const float* w_dq      = (const float*)d_in[1];
    const float* q_a_norm  = (const float*)d_in[2];
    const float* w_uq      = (const float*)d_in[3];
    const float* w_dkv     = (const float*)d_in[4];
    const float* kv_a_norm = (const float*)d_in[5];
    const float* w_ukv     = (const float*)d_in[6];
    const float* w_o       = (const float*)d_in[7];
    float* out = (float*)d_out;

    float *qa, *q, *ckv, *kv, *o;
    cudaGetSymbolAddress((void**)&qa,  g_qa);
    cudaGetSymbolAddress((void**)&q,   g_q);
    cudaGetSymbolAddress((void**)&ckv, g_ckv);
    cudaGetSymbolAddress((void**)&kv,  g_kv);
    cudaGetSymbolAddress((void**)&o,   g_o);

    // q_a = x @ w_dq          [4096,2048]@[2048,1536]
    sgemm_k<<<dim3(Q_RANK/BN, RR/BM), 256>>>(x, w_dq, qa, RR, Q_RANK, DD, DD, Q_RANK, Q_RANK);
    // rmsnorm(q_a)
    rmsnorm_k<<<RR, 256>>>(qa, q_a_norm, Q_RANK, Q_RANK);
    // q = qa @ w_uq           [4096,1536]@[1536,3072]
    sgemm_k<<<dim3(HQ/BN, RR/BM), 256>>>(qa, w_uq, q, RR, HQ, Q_RANK, Q_RANK, HQ, HQ);
    // ckv = x @ w_dkv         [4096,2048]@[2048,576]
    sgemm_k<<<dim3((CKVW+BN-1)/BN, RR/BM), 256>>>(x, w_dkv, ckv, RR, CKVW, DD, DD, CKVW, CKVW);
    // rmsnorm on first 512 cols of ckv
    rmsnorm_k<<<RR, 256>>>(ckv, kv_a_norm, KV_RANK, CKVW);
    // rope k_pe (cols 512..575 of ckv)
    rope_kpe_k<<<(RR*32)/256, 256>>>();
    // kv = ckv[:, :512] @ w_ukv   [4096,512]@[512,4096]
    sgemm_k<<<dim3(HKV/BN, RR/BM), 256>>>(ckv, w_ukv, kv, RR, HKV, KV_RANK, CKVW, HKV, HKV);
    // rope q_pe
    rope_q_k<<<(RR*HH*32)/256, 256>>>();
    // attention
    flash_k<<<dim3(SS/8, HH, BB), 256>>>();
    // out = o @ w_o           [4096,2048]@[2048,2048]
    sgemm_k<<<dim3(DD/BN, RR/BM), 256>>>(o, w_o, out, RR, DD, OW, OW, DD, DD);
}

// round 14
// speedup vs baseline: 1.6683x; 1.6683x over previous
#include <cuda_runtime.h>
#include <cuda_bf16.h>
#include <math.h>
#include <stdint.h>

// Problem constants
#define BB 2
#define SS 2048
#define DD 2048
#define HH 16
#define NOPE 128
#define ROPE 64
#define VD 128
#define KV_RANK 512
#define Q_RANK 1536
#define RR (BB*SS)          // 4096 rows
#define QD (NOPE+ROPE)      // 192
#define HQ (HH*QD)          // 3072
#define KVD (NOPE+VD)       // 256
#define HKV (HH*KVD)        // 4096
#define CKVW (KV_RANK+ROPE) // 576
#define OW (HH*VD)          // 2048

// fp32 scratch
__device__ float g_qa [(size_t)RR*Q_RANK];
__device__ float g_q  [(size_t)RR*HQ];
__device__ float g_ckv[(size_t)RR*CKVW];
__device__ float g_kv [(size_t)RR*HKV];
__device__ float g_o  [(size_t)RR*OW];

// bf16 hi/lo scratch (A operands, row-major [M,K])
__device__ __nv_bfloat16 g_xh [(size_t)RR*DD],      g_xl [(size_t)RR*DD];
__device__ __nv_bfloat16 g_qah[(size_t)RR*Q_RANK],  g_qal[(size_t)RR*Q_RANK];
__device__ __nv_bfloat16 g_ckh[(size_t)RR*KV_RANK], g_ckl[(size_t)RR*KV_RANK];
__device__ __nv_bfloat16 g_oh [(size_t)RR*OW],      g_ol [(size_t)RR*OW];
// bf16 hi/lo transposed weights (B operands, [N,K] K-major)
__device__ __nv_bfloat16 g_wdqh [(size_t)Q_RANK*DD],  g_wdql [(size_t)Q_RANK*DD];
__device__ __nv_bfloat16 g_wuqh [(size_t)HQ*Q_RANK],  g_wuql [(size_t)HQ*Q_RANK];
__device__ __nv_bfloat16 g_wdkvh[(size_t)CKVW*DD],    g_wdkvl[(size_t)CKVW*DD];
__device__ __nv_bfloat16 g_wukvh[(size_t)HKV*KV_RANK],g_wukvl[(size_t)HKV*KV_RANK];
__device__ __nv_bfloat16 g_woh  [(size_t)DD*OW],      g_wol  [(size_t)DD*OW];

// ---------------------------------------------------------------------------
// helpers
// ---------------------------------------------------------------------------
__device__ __forceinline__ uint32_t smem_u32(const void* p) {
    uint32_t a;
    asm("{ .reg .u64 t; cvta.to.shared.u64 t, %1; cvt.u32.u64 %0, t; }" : "=r"(a) : "l"(p));
    return a;
}
__device__ __forceinline__ void cp16(uint32_t dst, const void* src, uint32_t bytes) {
    asm volatile("cp.async.cg.shared.global [%0], [%1], 16, %2;\n"
                 :: "r"(dst), "l"(src), "r"(bytes) : "memory");
}
#define LDSM4(r, a) asm volatile( \
    "ldmatrix.sync.aligned.m8n8.x4.shared.b16 {%0,%1,%2,%3}, [%4];" \
    : "=r"((r)[0]),"=r"((r)[1]),"=r"((r)[2]),"=r"((r)[3]) : "r"(a))
#define MMA16816(c, a, b0, b1) asm volatile( \
    "mma.sync.aligned.m16n8k16.row.col.f32.bf16.bf16.f32 " \
    "{%0,%1,%2,%3}, {%4,%5,%6,%7}, {%8,%9}, {%0,%1,%2,%3};" \
    : "+f"((c)[0]),"+f"((c)[1]),"+f"((c)[2]),"+f"((c)[3]) \
    : "r"((a)[0]),"r"((a)[1]),"r"((a)[2]),"r"((a)[3]), "r"(b0),"r"(b1))

// ---------------------------------------------------------------------------
// HMMA bf16x3 GEMM: C[M,N](fp32) = A @ B^T.  A hi/lo [M,K], B hi/lo [N,K].
// Tile 128x128, BK=32, 8 warps (2x4), warp tile 64x32, 4-stage cp.async.
// SMEM rows padded to 80B (32 bf16 + 16B) -> ldmatrix conflict-free.
// ---------------------------------------------------------------------------
#define G_PITCH 80
#define G_TILE  (128*G_PITCH)   // 10240
#define G_STAGE (4*G_TILE)      // 40960: Ah, Al, Bh, Bl
#define G_SMEM  (4*G_STAGE)     // 163840

__global__ __launch_bounds__(256, 1) void gemm3_k(
    const __nv_bfloat16* __restrict__ Ah, const __nv_bfloat16* __restrict__ Al,
    const __nv_bfloat16* __restrict__ Bh, const __nv_bfloat16* __restrict__ Bl,
    float* __restrict__ C, int M, int N, int K)
{
    extern __shared__ __align__(128) char smem[];
    const uint32_t sb = smem_u32(smem);
    const int tid = threadIdx.x;
    const int wid = tid >> 5, lane = tid & 31;
    const int wm = wid >> 2, wn = wid & 3;       // 2 x 4 warps
    const int m0 = blockIdx.y * 128, n0 = blockIdx.x * 128;
    const int NK = K >> 5;

    float acc[4][4][4];
    #pragma unroll
    for (int i = 0; i < 4; i++)
        #pragma unroll
        for (int j = 0; j < 4; j++)
            #pragma unroll
            for (int e = 0; e < 4; e++) acc[i][j][e] = 0.f;

    auto load_stage = [&](int s, int kc) {
        uint32_t st = sb + s * G_STAGE;
        const int kcol = kc * 32;
        #pragma unroll
        for (int u = 0; u < 8; u++) {
            int id  = ((u & 1) << 8) + tid;     // 0..511
            int row = id >> 2, c = id & 3;
            uint32_t off = row * G_PITCH + c * 16;
            if (u < 2) {
                cp16(st + off, Ah + (size_t)(m0 + row) * K + kcol + c * 8, 16);
            } else if (u < 4) {
                cp16(st + G_TILE + off, Al + (size_t)(m0 + row) * K + kcol + c * 8, 16);
            } else {
                int nr = n0 + row;
                uint32_t ok = (nr < N) ? 16u : 0u;
                int nrc = (nr < N) ? nr : 0;
                const __nv_bfloat16* p = (u < 6) ? Bh : Bl;
                uint32_t to = (u < 6) ? 2*G_TILE : 3*G_TILE;
                cp16(st + to + off, p + (size_t)nrc * K + kcol + c * 8, ok);
            }
        }
        asm volatile("cp.async.commit_group;" ::: "memory");
    };

    load_stage(0, 0);
    load_stage(1, 1);
    load_stage(2, 2);

    const int lm_row = lane & 15;
    const uint32_t lm_k = ((lane >> 4) << 3);    // 0 or 8 (elements)

    for (int kc = 0; kc < NK; kc++) {
        asm volatile("cp.async.wait_group 2;" ::: "memory");
        __syncthreads();

        uint32_t st = sb + (kc & 3) * G_STAGE;
        #pragma unroll
        for (int k16 = 0; k16 < 2; k16++) {
            uint32_t koff = (k16 * 16 + lm_k) * 2;
            uint32_t ah[4][4], al[4][4];
            #pragma unroll
            for (int mi = 0; mi < 4; mi++) {
                uint32_t ro = (wm * 64 + mi * 16 + lm_row) * G_PITCH + koff;
                LDSM4(ah[mi], st + ro);
                LDSM4(al[mi], st + G_TILE + ro);
            }
            uint32_t bh[2][4], bl[2][4];
            #pragma unroll
            for (int nj = 0; nj < 2; nj++) {
                uint32_t ro = (wn * 32 + nj * 16 + lm_row) * G_PITCH + koff;
                LDSM4(bh[nj], st + 2*G_TILE + ro);
                LDSM4(bl[nj], st + 3*G_TILE + ro);
            }
            #pragma unroll
            for (int mi = 0; mi < 4; mi++)
                #pragma unroll
                for (int n = 0; n < 4; n++) {
                    int nj = n >> 1, h = n & 1;
                    uint32_t b0h = bh[nj][h], b1h = bh[nj][h + 2];
                    uint32_t b0l = bl[nj][h], b1l = bl[nj][h + 2];
                    MMA16816(acc[mi][n], ah[mi], b0h, b1h);
                    MMA16816(acc[mi][n], ah[mi], b0l, b1l);
                    MMA16816(acc[mi][n], al[mi], b0h, b1h);
                }
        }
        __syncthreads();
        int nk = kc + 3;
        if (nk < NK) load_stage(nk & 3, nk);
    }

    // epilogue
    const int r0 = lane >> 2, cp = (lane & 3) * 2;
    #pragma unroll
    for (int mi = 0; mi < 4; mi++) {
        int row = m0 + wm * 64 + mi * 16 + r0;
        #pragma unroll
        for (int n = 0; n < 4; n++) {
            int col = n0 + wn * 32 + n * 8 + cp;
            if (col < N) {
                *(float2*)(C + (size_t)row * N + col)       = make_float2(acc[mi][n][0], acc[mi][n][1]);
                *(float2*)(C + (size_t)(row + 8) * N + col) = make_float2(acc[mi][n][2], acc[mi][n][3]);
            }
        }
    }
}

// ---------------------------------------------------------------------------
// fp32 -> bf16 hi/lo split
// ---------------------------------------------------------------------------
__global__ __launch_bounds__(256) void split_k(
    const float* __restrict__ in, __nv_bfloat16* __restrict__ hi,
    __nv_bfloat16* __restrict__ lo, int cols, int stride)
{
    int row = blockIdx.y;
    int c = blockIdx.x * 256 + threadIdx.x;
    float v = in[(size_t)row * stride + c];
    __nv_bfloat16 h = __float2bfloat16(v);
    hi[(size_t)row * cols + c] = h;
    lo[(size_t)row * cols + c] = __float2bfloat16(v - __bfloat162float(h));
}

// transpose + split: in fp32 [K,N] -> out bf16 [N,K] hi/lo
__global__ __launch_bounds__(256) void tsplit_k(
    const float* __restrict__ in, __nv_bfloat16* __restrict__ hi,
    __nv_bfloat16* __restrict__ lo, int K, int N)
{
    __shared__ float tile[32][33];
    int kb = blockIdx.x * 32, nb = blockIdx.y * 32;
    int tx = threadIdx.x & 31, ty = threadIdx.x >> 5;   // 32x8
    for (int r = ty; r < 32; r += 8)
        tile[r][tx] = in[(size_t)(kb + r) * N + nb + tx];
    __syncthreads();
    for (int r = ty; r < 32; r += 8) {
        float v = tile[tx][r];
        __nv_bfloat16 h = __float2bfloat16(v);
        size_t o = (size_t)(nb + r) * K + kb + tx;
        hi[o] = h;
        lo[o] = __float2bfloat16(v - __bfloat162float(h));
    }
}

// ---------------------------------------------------------------------------
// RMSNorm (in place)
// ---------------------------------------------------------------------------
__global__ __launch_bounds__(256) void rmsnorm_k(
    float* __restrict__ x, const float* __restrict__ w, int n, int stride)
{
    int row = blockIdx.x;
    float* p = x + (size_t)row * stride;
    float ss = 0.f;
    for (int i = threadIdx.x; i < n; i += 256) { float v = p[i]; ss += v*v; }
    __shared__ float red[256];
    red[threadIdx.x] = ss;
    __syncthreads();
    for (int s2 = 128; s2 > 0; s2 >>= 1) {
        if (threadIdx.x < s2) red[threadIdx.x] += red[threadIdx.x + s2];
        __syncthreads();
    }
    float r = rsqrtf(red[0] / (float)n + 1e-6f);
    for (int i = threadIdx.x; i < n; i += 256) p[i] = p[i] * r * w[i];
}

// ---------------------------------------------------------------------------
// RoPE
// ---------------------------------------------------------------------------
__global__ void rope_q_k()
{
    int t = blockIdx.x * blockDim.x + threadIdx.x;
    int i = t & 31;
    int h = (t >> 5) & (HH-1);
    int r = t >> 9;
    int s = r & (SS-1);
    float inv = (float)pow(10000.0, -(double)(2*i) / 64.0);
    float ang = (float)s * inv;
    float sn, cs; sincosf(ang, &sn, &cs);
    float* p = &g_q[(size_t)r*HQ + h*QD + NOPE + i];
    float x1 = p[0], x2 = p[32];
    p[0]  = x1*cs - x2*sn;
    p[32] = x2*cs + x1*sn;
}
__global__ void rope_kpe_k()
{
    int t = blockIdx.x * blockDim.x + threadIdx.x;
    int i = t & 31;
    int r = t >> 5;
    int s = r & (SS-1);
    float inv = (float)pow(10000.0, -(double)(2*i) / 64.0);
    float ang = (float)s * inv;
    float sn, cs; sincosf(ang, &sn, &cs);
    float* p = &g_ckv[(size_t)r*CKVW + KV_RANK + i];
    float x1 = p[0], x2 = p[32];
    p[0]  = x1*cs - x2*sn;
    p[32] = x2*cs + x1*sn;
}

// ---------------------------------------------------------------------------
// Flash attention (causal), 16 query rows / block (2 per warp), 32-key tiles.
// Dynamic smem: Qs 16x192, Ks 32x196, Vs 32x128 = 53760 B.
// ---------------------------------------------------------------------------
#define FL_SMEM ((16*192 + 32*196 + 32*128) * 4)

__global__ __launch_bounds__(256) void flash_k()
{
    extern __shared__ float fsm[];
    float (*Qs)[192] = (float(*)[192])fsm;
    float (*Ks)[196] = (float(*)[196])(fsm + 16*192);
    float (*Vs)[128] = (float(*)[128])(fsm + 16*192 + 32*196);

    const int b = blockIdx.z, h = blockIdx.y;
    const int q0 = blockIdx.x * 16;
    const int tid = threadIdx.x;
    const int w = tid >> 5, lane = tid & 31;

    for (int idx = tid; idx < 16*192; idx += 256) {
        int row = idx / 192, d = idx - row*192;
        Qs[row][d] = g_q[(size_t)(b*SS + q0 + row)*HQ + h*QD + d];
    }

    const int qiA = q0 + w;        // rows w and w+8
    const int qiB = q0 + w + 8;
    float mA = -1e30f, lA = 0.f, mB = -1e30f, lB = 0.f;
    float oA0=0.f,oA1=0.f,oA2=0.f,oA3=0.f;
    float oB0=0.f,oB1=0.f,oB2=0.f,oB3=0.f;
    const float scale = rsqrtf((float)QD);
    const int ntiles = (q0 + 15) / 32 + 1;

    for (int kt = 0; kt < ntiles; kt++) {
        const int k0 = kt * 32;
        __syncthreads();
        for (int idx = tid; idx < 32*192; idx += 256) {
            int j = idx / 192, d = idx - j*192;
            size_t rk = (size_t)(b*SS + k0 + j);
            Ks[j][d] = (d < NOPE) ? g_kv[rk*HKV + h*KVD + d]
                                  : g_ckv[rk*CKVW + KV_RANK + (d - NOPE)];
        }
        for (int idx = tid; idx < 32*128; idx += 256) {
            int j = idx >> 7, d = idx & 127;
            Vs[j][d] = g_kv[(size_t)(b*SS + k0 + j)*HKV + h*KVD + NOPE + d];
        }
        __syncthreads();

        float sA = 0.f, sB = 0.f;
        const float4* kp  = (const float4*)&Ks[lane][0];
        const float4* qpA = (const float4*)&Qs[w][0];
        const float4* qpB = (const float4*)&Qs[w+8][0];
        #pragma unroll
        for (int d4 = 0; d4 < 48; d4++) {
            float4 kk = kp[d4];
            float4 qa = qpA[d4], qb = qpB[d4];
            sA = fmaf(kk.x, qa.x, sA); sB = fmaf(kk.x, qb.x, sB);
            sA = fmaf(kk.y, qa.y, sA); sB = fmaf(kk.y, qb.y, sB);
            sA = fmaf(kk.z, qa.z, sA); sB = fmaf(kk.z, qb.z, sB);
            sA = fmaf(kk.w, qa.w, sA); sB = fmaf(kk.w, qb.w, sB);
        }
        sA *= scale; sB *= scale;
        if (k0 + lane > qiA) sA = -1e30f;
        if (k0 + lane > qiB) sB = -1e30f;

        float mxA = sA, mxB = sB;
        #pragma unroll
        for (int off = 16; off; off >>= 1) {
            mxA = fmaxf(mxA, __shfl_xor_sync(0xffffffffu, mxA, off));
            mxB = fmaxf(mxB, __shfl_xor_sync(0xffffffffu, mxB, off));
        }
        float mnA = fmaxf(mA, mxA), mnB = fmaxf(mB, mxB);
        float aA = __expf(mA - mnA), aB = __expf(mB - mnB);
        float pA = __expf(sA - mnA), pB = __expf(sB - mnB);
        float psA = pA, psB = pB;
        #pragma unroll
        for (int off = 16; off; off >>= 1) {
            psA += __shfl_xor_sync(0xffffffffu, psA, off);
            psB += __shfl_xor_sync(0xffffffffu, psB, off);
        }
        lA = lA * aA + psA;  lB = lB * aB + psB;
        oA0 *= aA; oA1 *= aA; oA2 *= aA; oA3 *= aA;
        oB0 *= aB; oB1 *= aB; oB2 *= aB; oB3 *= aB;
        mA = mnA; mB = mnB;

        #pragma unroll
        for (int j = 0; j < 32; j++) {
            float wA = __shfl_sync(0xffffffffu, pA, j);
            float wB = __shfl_sync(0xffffffffu, pB, j);
            float v0 = Vs[j][lane      ];
            float v1 = Vs[j][lane + 32 ];
            float v2 = Vs[j][lane + 64 ];
            float v3 = Vs[j][lane + 96 ];
            oA0 = fmaf(wA, v0, oA0);  oB0 = fmaf(wB, v0, oB0);
            oA1 = fmaf(wA, v1, oA1);  oB1 = fmaf(wB, v1, oB1);
            oA2 = fmaf(wA, v2, oA2);  oB2 = fmaf(wB, v2, oB2);
            oA3 = fmaf(wA, v3, oA3);  oB3 = fmaf(wB, v3, oB3);
        }
    }

    float ivA = 1.f / lA, ivB = 1.f / lB;
    float* opA = &g_o[(size_t)(b*SS + qiA)*OW + h*VD];
    float* opB = &g_o[(size_t)(b*SS + qiB)*OW + h*VD];
    opA[lane] = oA0*ivA; opA[lane+32] = oA1*ivA; opA[lane+64] = oA2*ivA; opA[lane+96] = oA3*ivA;
    opB[lane] = oB0*ivB; opB[lane+32] = oB1*ivB; opB[lane+64] = oB2*ivB; opB[lane+96] = oB3*ivB;
}

// ---------------------------------------------------------------------------
// Launch
// ---------------------------------------------------------------------------
static inline void launch_gemm(const __nv_bfloat16* Ah, const __nv_bfloat16* Al,
                               const __nv_bfloat16* Bh, const __nv_bfloat16* Bl,
                               float* C, int M, int N, int K)
{
    dim3 grid((N + 127) / 128, M / 128);
    gemm3_k<<<grid, 256, G_SMEM>>>(Ah, Al, Bh, Bl, C, M, N, K);
}

extern "C" void kernel_launch(void* const* d_in, const int* in_sizes, int n_in,
                              void* d_out, int out_size)
{
    const float* x         = (const float*)d_in[0];
    const float* w_dq      = (const float*)d_in[1];
    const float* q_a_norm  = (const float*)d_in[2];
    const float* w_uq      = (const float*)d_in[3];
    const float* w_dkv     = (const float*)d_in[4];
    const float* kv_a_norm = (const float*)d_in[5];
    const float* w_ukv     = (const float*)d_in[6];
    const float* w_o       = (const float*)d_in[7];
    float* out = (float*)d_out;

    cudaFuncSetAttribute(gemm3_k, cudaFuncAttributeMaxDynamicSharedMemorySize, G_SMEM);
    cudaFuncSetAttribute(flash_k, cudaFuncAttributeMaxDynamicSharedMemorySize, FL_SMEM);

    float *qa, *q, *ckv, *kv, *o;
    cudaGetSymbolAddress((void**)&qa,  g_qa);
    cudaGetSymbolAddress((void**)&q,   g_q);
    cudaGetSymbolAddress((void**)&ckv, g_ckv);
    cudaGetSymbolAddress((void**)&kv,  g_kv);
    cudaGetSymbolAddress((void**)&o,   g_o);
    __nv_bfloat16 *xh,*xl,*qah,*qal,*ckh,*ckl,*oh,*ol;
    __nv_bfloat16 *wdqh,*wdql,*wuqh,*wuql,*wdkvh,*wdkvl,*wukvh,*wukvl,*woh,*wol;
    cudaGetSymbolAddress((void**)&xh, g_xh);   cudaGetSymbolAddress((void**)&xl, g_xl);
    cudaGetSymbolAddress((void**)&qah,g_qah);  cudaGetSymbolAddress((void**)&qal,g_qal);
    cudaGetSymbolAddress((void**)&ckh,g_ckh);  cudaGetSymbolAddress((void**)&ckl,g_ckl);
    cudaGetSymbolAddress((void**)&oh, g_oh);   cudaGetSymbolAddress((void**)&ol, g_ol);
    cudaGetSymbolAddress((void**)&wdqh,g_wdqh);   cudaGetSymbolAddress((void**)&wdql,g_wdql);
    cudaGetSymbolAddress((void**)&wuqh,g_wuqh);   cudaGetSymbolAddress((void**)&wuql,g_wuql);
    cudaGetSymbolAddress((void**)&wdkvh,g_wdkvh); cudaGetSymbolAddress((void**)&wdkvl,g_wdkvl);
    cudaGetSymbolAddress((void**)&wukvh,g_wukvh); cudaGetSymbolAddress((void**)&wukvl,g_wukvl);
    cudaGetSymbolAddress((void**)&woh,g_woh);     cudaGetSymbolAddress((void**)&wol,g_wol);

    // Weight transpose+split
    tsplit_k<<<dim3(DD/32,      Q_RANK/32), 256>>>(w_dq,  wdqh,  wdql,  DD,      Q_RANK);
    tsplit_k<<<dim3(Q_RANK/32,  HQ/32),     256>>>(w_uq,  wuqh,  wuql,  Q_RANK,  HQ);
    tsplit_k<<<dim3(DD/32,      CKVW/32),   256>>>(w_dkv, wdkvh, wdkvl, DD,      CKVW);
    tsplit_k<<<dim3(KV_RANK/32, HKV/32),    256>>>(w_ukv, wukvh, wukvl, KV_RANK, HKV);
    tsplit_k<<<dim3(OW/32,      DD/32),     256>>>(w_o,   woh,   wol,   OW,      DD);

    // x split
    split_k<<<dim3(DD/256, RR), 256>>>(x, xh, xl, DD, DD);

    // qa = x @ w_dq ; rmsnorm ; split
    launch_gemm(xh, xl, wdqh, wdql, qa, RR, Q_RANK, DD);
    rmsnorm_k<<<RR, 256>>>(qa, q_a_norm, Q_RANK, Q_RANK);
    split_k<<<dim3(Q_RANK/256, RR), 256>>>(qa, qah, qal, Q_RANK, Q_RANK);

    // q = qa @ w_uq
    launch_gemm(qah, qal, wuqh, wuql, q, RR, HQ, Q_RANK);

    // ckv = x @ w_dkv ; rmsnorm(512) ; rope k_pe ; split first 512 cols
    launch_gemm(xh, xl, wdkvh, wdkvl, ckv, RR, CKVW, DD);
    rmsnorm_k<<<RR, 256>>>(ckv, kv_a_norm, KV_RANK, CKVW);
    rope_kpe_k<<<(RR*32)/256, 256>>>();
    split_k<<<dim3(KV_RANK/256, RR), 256>>>(ckv, ckh, ckl, KV_RANK, CKVW);

    // kv = ckv512 @ w_ukv
    launch_gemm(ckh, ckl, wukvh, wukvl, kv, RR, HKV, KV_RANK);

    // rope q, attention
    rope_q_k<<<(RR*HH*32)/256, 256>>>();
    flash_k<<<dim3(SS/16, HH, BB), 256, FL_SMEM>>>();

    // out = o @ w_o
    split_k<<<dim3(OW/256, RR), 256>>>(o, oh, ol, OW, OW);
    launch_gemm(oh, ol, woh, wol, out, RR, DD, OW);
}

// round 16
// speedup vs baseline: 1.6769x; 1.0051x over previous
#include <cuda_runtime.h>
#include <cuda_bf16.h>
#include <math.h>
#include <stdint.h>

// Problem constants
#define BB 2
#define SS 2048
#define DD 2048
#define HH 16
#define NOPE 128
#define ROPE 64
#define VD 128
#define KV_RANK 512
#define Q_RANK 1536
#define RR (BB*SS)          // 4096 rows
#define QD (NOPE+ROPE)      // 192
#define HQ (HH*QD)          // 3072
#define KVD (NOPE+VD)       // 256
#define HKV (HH*KVD)        // 4096
#define CKVW (KV_RANK+ROPE) // 576
#define OW (HH*VD)          // 2048

// fp32 scratch
__device__ float g_qa [(size_t)RR*Q_RANK];
__device__ float g_q  [(size_t)RR*HQ];
__device__ float g_ckv[(size_t)RR*CKVW];
__device__ float g_kv [(size_t)RR*HKV];

// bf16 hi/lo scratch (A operands, row-major [M,K])
__device__ __nv_bfloat16 g_xh [(size_t)RR*DD],      g_xl [(size_t)RR*DD];
__device__ __nv_bfloat16 g_qah[(size_t)RR*Q_RANK],  g_qal[(size_t)RR*Q_RANK];
__device__ __nv_bfloat16 g_ckh[(size_t)RR*KV_RANK], g_ckl[(size_t)RR*KV_RANK];
__device__ __nv_bfloat16 g_oh [(size_t)RR*OW],      g_ol [(size_t)RR*OW];
// bf16 hi/lo transposed weights (B operands, [N,K] K-major)
__device__ __nv_bfloat16 g_wdqh [(size_t)Q_RANK*DD],  g_wdql [(size_t)Q_RANK*DD];
__device__ __nv_bfloat16 g_wuqh [(size_t)HQ*Q_RANK],  g_wuql [(size_t)HQ*Q_RANK];
__device__ __nv_bfloat16 g_wdkvh[(size_t)CKVW*DD],    g_wdkvl[(size_t)CKVW*DD];
__device__ __nv_bfloat16 g_wukvh[(size_t)HKV*KV_RANK],g_wukvl[(size_t)HKV*KV_RANK];
__device__ __nv_bfloat16 g_woh  [(size_t)DD*OW],      g_wol  [(size_t)DD*OW];

// ---------------------------------------------------------------------------
// helpers
// ---------------------------------------------------------------------------
__device__ __forceinline__ uint32_t smem_u32(const void* p) {
    uint32_t a;
    asm("{ .reg .u64 t; cvta.to.shared.u64 t, %1; cvt.u32.u64 %0, t; }" : "=r"(a) : "l"(p));
    return a;
}
__device__ __forceinline__ void cp16(uint32_t dst, const void* src, uint32_t bytes) {
    asm volatile("cp.async.cg.shared.global [%0], [%1], 16, %2;\n"
                 :: "r"(dst), "l"(src), "r"(bytes) : "memory");
}
#define LDSM4(r, a) asm volatile( \
    "ldmatrix.sync.aligned.m8n8.x4.shared.b16 {%0,%1,%2,%3}, [%4];" \
    : "=r"((r)[0]),"=r"((r)[1]),"=r"((r)[2]),"=r"((r)[3]) : "r"(a))
#define MMA16816(c, a, b0, b1) asm volatile( \
    "mma.sync.aligned.m16n8k16.row.col.f32.bf16.bf16.f32 " \
    "{%0,%1,%2,%3}, {%4,%5,%6,%7}, {%8,%9}, {%0,%1,%2,%3};" \
    : "+f"((c)[0]),"+f"((c)[1]),"+f"((c)[2]),"+f"((c)[3]) \
    : "r"((a)[0]),"r"((a)[1]),"r"((a)[2]),"r"((a)[3]), "r"(b0),"r"(b1))

// ---------------------------------------------------------------------------
// HMMA bf16x3 GEMM: C[M,N](fp32) = A @ B^T.  A hi/lo [M,K], B hi/lo [N,K].
// Tile 128x128, BK=32, 8 warps (2x4), warp tile 64x32, 4-stage cp.async.
// ---------------------------------------------------------------------------
#define G_PITCH 80
#define G_TILE  (128*G_PITCH)   // 10240
#define G_STAGE (4*G_TILE)      // 40960: Ah, Al, Bh, Bl
#define G_SMEM  (4*G_STAGE)     // 163840

__global__ __launch_bounds__(256, 1) void gemm3_k(
    const __nv_bfloat16* __restrict__ Ah, const __nv_bfloat16* __restrict__ Al,
    const __nv_bfloat16* __restrict__ Bh, const __nv_bfloat16* __restrict__ Bl,
    float* __restrict__ C, int M, int N, int K)
{
    extern __shared__ __align__(128) char smem[];
    const uint32_t sb = smem_u32(smem);
    const int tid = threadIdx.x;
    const int wid = tid >> 5, lane = tid & 31;
    const int wm = wid >> 2, wn = wid & 3;       // 2 x 4 warps
    const int m0 = blockIdx.y * 128, n0 = blockIdx.x * 128;
    const int NK = K >> 5;

    float acc[4][4][4];
    #pragma unroll
    for (int i = 0; i < 4; i++)
        #pragma unroll
        for (int j = 0; j < 4; j++)
            #pragma unroll
            for (int e = 0; e < 4; e++) acc[i][j][e] = 0.f;

    auto load_stage = [&](int s, int kc) {
        uint32_t st = sb + s * G_STAGE;
        const int kcol = kc * 32;
        #pragma unroll
        for (int u = 0; u < 8; u++) {
            int id  = ((u & 1) << 8) + tid;     // 0..511
            int row = id >> 2, c = id & 3;
            uint32_t off = row * G_PITCH + c * 16;
            if (u < 2) {
                cp16(st + off, Ah + (size_t)(m0 + row) * K + kcol + c * 8, 16);
            } else if (u < 4) {
                cp16(st + G_TILE + off, Al + (size_t)(m0 + row) * K + kcol + c * 8, 16);
            } else {
                int nr = n0 + row;
                uint32_t ok = (nr < N) ? 16u : 0u;
                int nrc = (nr < N) ? nr : 0;
                const __nv_bfloat16* p = (u < 6) ? Bh : Bl;
                uint32_t to = (u < 6) ? 2*G_TILE : 3*G_TILE;
                cp16(st + to + off, p + (size_t)nrc * K + kcol + c * 8, ok);
            }
        }
        asm volatile("cp.async.commit_group;" ::: "memory");
    };

    load_stage(0, 0);
    load_stage(1, 1);
    load_stage(2, 2);

    const int lm_row = lane & 15;
    const uint32_t lm_k = ((lane >> 4) << 3);    // 0 or 8 (elements)

    for (int kc = 0; kc < NK; kc++) {
        asm volatile("cp.async.wait_group 2;" ::: "memory");
        __syncthreads();

        uint32_t st = sb + (kc & 3) * G_STAGE;
        #pragma unroll
        for (int k16 = 0; k16 < 2; k16++) {
            uint32_t koff = (k16 * 16 + lm_k) * 2;
            uint32_t ah[4][4], al[4][4];
            #pragma unroll
            for (int mi = 0; mi < 4; mi++) {
                uint32_t ro = (wm * 64 + mi * 16 + lm_row) * G_PITCH + koff;
                LDSM4(ah[mi], st + ro);
                LDSM4(al[mi], st + G_TILE + ro);
            }
            uint32_t bh[2][4], bl[2][4];
            #pragma unroll
            for (int nj = 0; nj < 2; nj++) {
                uint32_t ro = (wn * 32 + nj * 16 + lm_row) * G_PITCH + koff;
                LDSM4(bh[nj], st + 2*G_TILE + ro);
                LDSM4(bl[nj], st + 3*G_TILE + ro);
            }
            #pragma unroll
            for (int mi = 0; mi < 4; mi++)
                #pragma unroll
                for (int n = 0; n < 4; n++) {
                    int nj = n >> 1, h = n & 1;
                    uint32_t b0h = bh[nj][h], b1h = bh[nj][h + 2];
                    uint32_t b0l = bl[nj][h], b1l = bl[nj][h + 2];
                    MMA16816(acc[mi][n], ah[mi], b0h, b1h);
                    MMA16816(acc[mi][n], ah[mi], b0l, b1l);
                    MMA16816(acc[mi][n], al[mi], b0h, b1h);
                }
        }
        __syncthreads();
        int nk = kc + 3;
        if (nk < NK) load_stage(nk & 3, nk);
    }

    // epilogue
    const int r0 = lane >> 2, cp = (lane & 3) * 2;
    #pragma unroll
    for (int mi = 0; mi < 4; mi++) {
        int row = m0 + wm * 64 + mi * 16 + r0;
        #pragma unroll
        for (int n = 0; n < 4; n++) {
            int col = n0 + wn * 32 + n * 8 + cp;
            if (col < N) {
                *(float2*)(C + (size_t)row * N + col)       = make_float2(acc[mi][n][0], acc[mi][n][1]);
                *(float2*)(C + (size_t)(row + 8) * N + col) = make_float2(acc[mi][n][2], acc[mi][n][3]);
            }
        }
    }
}

// ---------------------------------------------------------------------------
// fp32 -> bf16 hi/lo split (x only)
// ---------------------------------------------------------------------------
__global__ __launch_bounds__(256) void split_k(
    const float* __restrict__ in, __nv_bfloat16* __restrict__ hi,
    __nv_bfloat16* __restrict__ lo, int cols, int stride)
{
    int row = blockIdx.y;
    int c = blockIdx.x * 256 + threadIdx.x;
    float v = in[(size_t)row * stride + c];
    __nv_bfloat16 h = __float2bfloat16(v);
    hi[(size_t)row * cols + c] = h;
    lo[(size_t)row * cols + c] = __float2bfloat16(v - __bfloat162float(h));
}

// ---------------------------------------------------------------------------
// Batched transpose+split: all 5 weights in ONE launch (blockIdx.z selects).
// in fp32 [K,N] -> out bf16 [N,K] hi/lo
// ---------------------------------------------------------------------------
struct TSArg {
    const float* in;
    __nv_bfloat16* hi;
    __nv_bfloat16* lo;
    int K, N;
};

__global__ __launch_bounds__(256) void tsplit_all_k(
    TSArg t0, TSArg t1, TSArg t2, TSArg t3, TSArg t4)
{
    TSArg t;
    switch (blockIdx.z) {
        case 0: t = t0; break;
        case 1: t = t1; break;
        case 2: t = t2; break;
        case 3: t = t3; break;
        default: t = t4; break;
    }
    int kb = blockIdx.x * 32, nb = blockIdx.y * 32;
    if (kb >= t.K || nb >= t.N) return;

    __shared__ float tile[32][33];
    int tx = threadIdx.x & 31, ty = threadIdx.x >> 5;   // 32x8
    for (int r = ty; r < 32; r += 8)
        tile[r][tx] = t.in[(size_t)(kb + r) * t.N + nb + tx];
    __syncthreads();
    for (int r = ty; r < 32; r += 8) {
        float v = tile[tx][r];
        __nv_bfloat16 h = __float2bfloat16(v);
        size_t o = (size_t)(nb + r) * t.K + kb + tx;
        t.hi[o] = h;
        t.lo[o] = __float2bfloat16(v - __bfloat162float(h));
    }
}

// ---------------------------------------------------------------------------
// RMSNorm fused with bf16 hi/lo split: reads fp32, writes ONLY hi/lo.
// ---------------------------------------------------------------------------
__global__ __launch_bounds__(256) void rmsnorm_split_k(
    const float* __restrict__ x, const float* __restrict__ w,
    __nv_bfloat16* __restrict__ hi, __nv_bfloat16* __restrict__ lo,
    int n, int stride, int ocols)
{
    int row = blockIdx.x;
    const float* p = x + (size_t)row * stride;
    float ss = 0.f;
    for (int i = threadIdx.x; i < n; i += 256) { float v = p[i]; ss += v*v; }
    __shared__ float red[256];
    red[threadIdx.x] = ss;
    __syncthreads();
    for (int s2 = 128; s2 > 0; s2 >>= 1) {
        if (threadIdx.x < s2) red[threadIdx.x] += red[threadIdx.x + s2];
        __syncthreads();
    }
    float r = rsqrtf(red[0] / (float)n + 1e-6f);
    for (int i = threadIdx.x; i < n; i += 256) {
        float v = p[i] * r * w[i];
        __nv_bfloat16 h = __float2bfloat16(v);
        hi[(size_t)row * ocols + i] = h;
        lo[(size_t)row * ocols + i] = __float2bfloat16(v - __bfloat162float(h));
    }
}

// ---------------------------------------------------------------------------
// RoPE
// ---------------------------------------------------------------------------
__global__ void rope_q_k()
{
    int t = blockIdx.x * blockDim.x + threadIdx.x;
    int i = t & 31;
    int h = (t >> 5) & (HH-1);
    int r = t >> 9;
    int s = r & (SS-1);
    float inv = (float)pow(10000.0, -(double)(2*i) / 64.0);
    float ang = (float)s * inv;
    float sn, cs; sincosf(ang, &sn, &cs);
    float* p = &g_q[(size_t)r*HQ + h*QD + NOPE + i];
    float x1 = p[0], x2 = p[32];
    p[0]  = x1*cs - x2*sn;
    p[32] = x2*cs + x1*sn;
}
__global__ void rope_kpe_k()
{
    int t = blockIdx.x * blockDim.x + threadIdx.x;
    int i = t & 31;
    int r = t >> 5;
    int s = r & (SS-1);
    float inv = (float)pow(10000.0, -(double)(2*i) / 64.0);
    float ang = (float)s * inv;
    float sn, cs; sincosf(ang, &sn, &cs);
    float* p = &g_ckv[(size_t)r*CKVW + KV_RANK + i];
    float x1 = p[0], x2 = p[32];
    p[0]  = x1*cs - x2*sn;
    p[32] = x2*cs + x1*sn;
}

// ---------------------------------------------------------------------------
// Flash attention (causal), 16 query rows / block (2 per warp), 32-key tiles.
// Writes bf16 hi/lo output directly (feeds final GEMM).
// ---------------------------------------------------------------------------
#define FL_SMEM ((16*192 + 32*196 + 32*128) * 4)

__global__ __launch_bounds__(256) void flash_k()
{
    extern __shared__ float fsm[];
    float (*Qs)[192] = (float(*)[192])fsm;
    float (*Ks)[196] = (float(*)[196])(fsm + 16*192);
    float (*Vs)[128] = (float(*)[128])(fsm + 16*192 + 32*196);

    const int b = blockIdx.z, h = blockIdx.y;
    const int q0 = blockIdx.x * 16;
    const int tid = threadIdx.x;
    const int w = tid >> 5, lane = tid & 31;

    for (int idx = tid; idx < 16*192; idx += 256) {
        int row = idx / 192, d = idx - row*192;
        Qs[row][d] = g_q[(size_t)(b*SS + q0 + row)*HQ + h*QD + d];
    }

    const int qiA = q0 + w;        // rows w and w+8
    const int qiB = q0 + w + 8;
    float mA = -1e30f, lA = 0.f, mB = -1e30f, lB = 0.f;
    float oA0=0.f,oA1=0.f,oA2=0.f,oA3=0.f;
    float oB0=0.f,oB1=0.f,oB2=0.f,oB3=0.f;
    const float scale = rsqrtf((float)QD);
    const int ntiles = (q0 + 15) / 32 + 1;

    for (int kt = 0; kt < ntiles; kt++) {
        const int k0 = kt * 32;
        __syncthreads();
        for (int idx = tid; idx < 32*192; idx += 256) {
            int j = idx / 192, d = idx - j*192;
            size_t rk = (size_t)(b*SS + k0 + j);
            Ks[j][d] = (d < NOPE) ? g_kv[rk*HKV + h*KVD + d]
                                  : g_ckv[rk*CKVW + KV_RANK + (d - NOPE)];
        }
        for (int idx = tid; idx < 32*128; idx += 256) {
            int j = idx >> 7, d = idx & 127;
            Vs[j][d] = g_kv[(size_t)(b*SS + k0 + j)*HKV + h*KVD + NOPE + d];
        }
        __syncthreads();

        float sA = 0.f, sB = 0.f;
        const float4* kp  = (const float4*)&Ks[lane][0];
        const float4* qpA = (const float4*)&Qs[w][0];
        const float4* qpB = (const float4*)&Qs[w+8][0];
        #pragma unroll
        for (int d4 = 0; d4 < 48; d4++) {
            float4 kk = kp[d4];
            float4 qa = qpA[d4], qb = qpB[d4];
            sA = fmaf(kk.x, qa.x, sA); sB = fmaf(kk.x, qb.x, sB);
            sA = fmaf(kk.y, qa.y, sA); sB = fmaf(kk.y, qb.y, sB);
            sA = fmaf(kk.z, qa.z, sA); sB = fmaf(kk.z, qb.z, sB);
            sA = fmaf(kk.w, qa.w, sA); sB = fmaf(kk.w, qb.w, sB);
        }
        sA *= scale; sB *= scale;
        if (k0 + lane > qiA) sA = -1e30f;
        if (k0 + lane > qiB) sB = -1e30f;

        float mxA = sA, mxB = sB;
        #pragma unroll
        for (int off = 16; off; off >>= 1) {
            mxA = fmaxf(mxA, __shfl_xor_sync(0xffffffffu, mxA, off));
            mxB = fmaxf(mxB, __shfl_xor_sync(0xffffffffu, mxB, off));
        }
        float mnA = fmaxf(mA, mxA), mnB = fmaxf(mB, mxB);
        float aA = __expf(mA - mnA), aB = __expf(mB - mnB);
        float pA = __expf(sA - mnA), pB = __expf(sB - mnB);
        float psA = pA, psB = pB;
        #pragma unroll
        for (int off = 16; off; off >>= 1) {
            psA += __shfl_xor_sync(0xffffffffu, psA, off);
            psB += __shfl_xor_sync(0xffffffffu, psB, off);
        }
        lA = lA * aA + psA;  lB = lB * aB + psB;
        oA0 *= aA; oA1 *= aA; oA2 *= aA; oA3 *= aA;
        oB0 *= aB; oB1 *= aB; oB2 *= aB; oB3 *= aB;
        mA = mnA; mB = mnB;

        #pragma unroll
        for (int j = 0; j < 32; j++) {
            float wA = __shfl_sync(0xffffffffu, pA, j);
            float wB = __shfl_sync(0xffffffffu, pB, j);
            float v0 = Vs[j][lane      ];
            float v1 = Vs[j][lane + 32 ];
            float v2 = Vs[j][lane + 64 ];
            float v3 = Vs[j][lane + 96 ];
            oA0 = fmaf(wA, v0, oA0);  oB0 = fmaf(wB, v0, oB0);
            oA1 = fmaf(wA, v1, oA1);  oB1 = fmaf(wB, v1, oB1);
            oA2 = fmaf(wA, v2, oA2);  oB2 = fmaf(wB, v2, oB2);
            oA3 = fmaf(wA, v3, oA3);  oB3 = fmaf(wB, v3, oB3);
        }
    }

    float ivA = 1.f / lA, ivB = 1.f / lB;
    size_t baseA = (size_t)(b*SS + qiA)*OW + h*VD;
    size_t baseB = (size_t)(b*SS + qiB)*OW + h*VD;
    float vals[8] = { oA0*ivA, oA1*ivA, oA2*ivA, oA3*ivA,
                      oB0*ivB, oB1*ivB, oB2*ivB, oB3*ivB };
    #pragma unroll
    for (int c = 0; c < 4; c++) {
        __nv_bfloat16 hA = __float2bfloat16(vals[c]);
        g_oh[baseA + lane + 32*c] = hA;
        g_ol[baseA + lane + 32*c] = __float2bfloat16(vals[c] - __bfloat162float(hA));
        __nv_bfloat16 hB = __float2bfloat16(vals[4+c]);
        g_oh[baseB + lane + 32*c] = hB;
        g_ol[baseB + lane + 32*c] = __float2bfloat16(vals[4+c] - __bfloat162float(hB));
    }
}

// ---------------------------------------------------------------------------
// Launch
// ---------------------------------------------------------------------------
static inline void launch_gemm(const __nv_bfloat16* Ah, const __nv_bfloat16* Al,
                               const __nv_bfloat16* Bh, const __nv_bfloat16* Bl,
                               float* C, int M, int N, int K)
{
    dim3 grid((N + 127) / 128, M / 128);
    gemm3_k<<<grid, 256, G_SMEM>>>(Ah, Al, Bh, Bl, C, M, N, K);
}

extern "C" void kernel_launch(void* const* d_in, const int* in_sizes, int n_in,
                              void* d_out, int out_size)
{
    const float* x         = (const float*)d_in[0];
    const float* w_dq      = (const float*)d_in[1];
    const float* q_a_norm  = (const float*)d_in[2];
    const float* w_uq      = (const float*)d_in[3];
    const float* w_dkv     = (const float*)d_in[4];
    const float* kv_a_norm = (const float*)d_in[5];
    const float* w_ukv     = (const float*)d_in[6];
    const float* w_o       = (const float*)d_in[7];
    float* out = (float*)d_out;

    cudaFuncSetAttribute(gemm3_k, cudaFuncAttributeMaxDynamicSharedMemorySize, G_SMEM);
    cudaFuncSetAttribute(flash_k, cudaFuncAttributeMaxDynamicSharedMemorySize, FL_SMEM);

    float *qa, *q, *ckv, *kv;
    cudaGetSymbolAddress((void**)&qa,  g_qa);
    cudaGetSymbolAddress((void**)&q,   g_q);
    cudaGetSymbolAddress((void**)&ckv, g_ckv);
    cudaGetSymbolAddress((void**)&kv,  g_kv);
    __nv_bfloat16 *xh,*xl,*qah,*qal,*ckh,*ckl,*oh,*ol;
    __nv_bfloat16 *wdqh,*wdql,*wuqh,*wuql,*wdkvh,*wdkvl,*wukvh,*wukvl,*woh,*wol;
    cudaGetSymbolAddress((void**)&xh, g_xh);   cudaGetSymbolAddress((void**)&xl, g_xl);
    cudaGetSymbolAddress((void**)&qah,g_qah);  cudaGetSymbolAddress((void**)&qal,g_qal);
    cudaGetSymbolAddress((void**)&ckh,g_ckh);  cudaGetSymbolAddress((void**)&ckl,g_ckl);
    cudaGetSymbolAddress((void**)&oh, g_oh);   cudaGetSymbolAddress((void**)&ol, g_ol);
    cudaGetSymbolAddress((void**)&wdqh,g_wdqh);   cudaGetSymbolAddress((void**)&wdql,g_wdql);
    cudaGetSymbolAddress((void**)&wuqh,g_wuqh);   cudaGetSymbolAddress((void**)&wuql,g_wuql);
    cudaGetSymbolAddress((void**)&wdkvh,g_wdkvh); cudaGetSymbolAddress((void**)&wdkvl,g_wdkvl);
    cudaGetSymbolAddress((void**)&wukvh,g_wukvh); cudaGetSymbolAddress((void**)&wukvl,g_wukvl);
    cudaGetSymbolAddress((void**)&woh,g_woh);     cudaGetSymbolAddress((void**)&wol,g_wol);

    // [0] All weight transpose+splits in ONE launch
    TSArg t0 = { w_dq,  wdqh,  wdql,  DD,      Q_RANK };
    TSArg t1 = { w_uq,  wuqh,  wuql,  Q_RANK,  HQ };
    TSArg t2 = { w_dkv, wdkvh, wdkvl, DD,      CKVW };
    TSArg t3 = { w_ukv, wukvh, wukvl, KV_RANK, HKV };
    TSArg t4 = { w_o,   woh,   wol,   OW,      DD };
    tsplit_all_k<<<dim3(DD/32, HKV/32, 5), 256>>>(t0, t1, t2, t3, t4);

    // [1] x split
    split_k<<<dim3(DD/256, RR), 256>>>(x, xh, xl, DD, DD);

    // [2] ckv = x @ w_dkv
    launch_gemm(xh, xl, wdkvh, wdkvl, ckv, RR, CKVW, DD);
    // [3] qa = x @ w_dq          <-- ncu capture slot (launch index 3)
    launch_gemm(xh, xl, wdqh, wdql, qa, RR, Q_RANK, DD);

    // [4] rmsnorm+split ckv -> ckh/ckl
    rmsnorm_split_k<<<RR, 256>>>(ckv, kv_a_norm, ckh, ckl, KV_RANK, CKVW, KV_RANK);
    // [5] rope k_pe (ckv fp32 cols 512..575)
    rope_kpe_k<<<(RR*32)/256, 256>>>();
    // [6] kv = ckv512 @ w_ukv
    launch_gemm(ckh, ckl, wukvh, wukvl, kv, RR, HKV, KV_RANK);

    // [7] rmsnorm+split qa -> qah/qal
    rmsnorm_split_k<<<RR, 256>>>(qa, q_a_norm, qah, qal, Q_RANK, Q_RANK, Q_RANK);
    // [8] q = qa @ w_uq
    launch_gemm(qah, qal, wuqh, wuql, q, RR, HQ, Q_RANK);
    // [9] rope q
    rope_q_k<<<(RR*HH*32)/256, 256>>>();

    // [10] attention -> oh/ol (bf16 hi/lo direct)
    flash_k<<<dim3(SS/16, HH, BB), 256, FL_SMEM>>>();

    // [11] out = o @ w_o
    launch_gemm(oh, ol, woh, wol, out, RR, DD, OW);
}